// round 4
// baseline (speedup 1.0000x reference)
#include <cuda_runtime.h>
#include <cstdint>

// Problem constants
#define B_DIM   128
#define OUT_DIM 1024
#define IN_DIM  1024

// Scratch: s[o,k] = d + a * sigmoid(dx * (w - x0))  (4 MB, static device array)
__device__ float g_sig[OUT_DIM * IN_DIM];

// ---------------------------------------------------------------------------
// Pipe-steering helpers. `one` is a runtime kernel argument equal to 1 so
// ptxas cannot fold it; mad.lo.u32 with multiplier `one` stays an IMAD on the
// fma pipe instead of an IADD3 on the alu pipe.
// ---------------------------------------------------------------------------
__device__ __forceinline__ uint32_t imad(uint32_t a, uint32_t b, uint32_t c) {
    uint32_t r;
    asm("mad.lo.u32 %0, %1, %2, %3;" : "=r"(r) : "r"(a), "r"(b), "r"(c));
    return r;
}
__device__ __forceinline__ uint32_t imul_lo(uint32_t a, uint32_t b) {
    uint32_t r;
    asm("mul.lo.u32 %0, %1, %2;" : "=r"(r) : "r"(a), "r"(b));
    return r;
}
__device__ __forceinline__ uint32_t imul_hi(uint32_t a, uint32_t b) {
    uint32_t r;
    asm("mul.hi.u32 %0, %1, %2;" : "=r"(r) : "r"(a), "r"(b));
    return r;
}
__device__ __forceinline__ uint32_t rotl32(uint32_t x, int r) {
    return __funnelshift_l(x, x, r);
}
// fma-pipe rotate: (x*2^r).lo | (x*2^r).hi, OR fused into the caller's LOP3 xor.
#define MROT_XOR(x1, m, x0) ((imul_lo((x1), (m)) | imul_hi((x1), (m))) ^ (x0))

// ---------------------------------------------------------------------------
// threefry2x32, key = (0, 42); partitionable random_bits:
//   ctr = (0, i), bits = out0 ^ out1.
//   ks1 = 42, ks2 = 42 ^ 0x1BD11BDA = 0x1BD11BF0
// Round adds + injections on IMAD (fma pipe); 6 of 20 rotates converted to
// mul-pair rotates (fma pipe) to balance alu vs fma vs issue.
// ---------------------------------------------------------------------------
__device__ __forceinline__ uint32_t threefry_bits_42(uint32_t i, uint32_t one,
                                                     uint32_t m15, uint32_t m26,
                                                     uint32_t m29) {
    const uint32_t ks1 = 42u, ks2 = 0x1BD11BF0u;

    uint32_t x1 = imad(i, one, ks1);   // setup (fma)
    uint32_t x0 = x1;                  // round-1 add with x0_init = 0 folded
    x1 = rotl32(x1, 13) ^ x0;                                   // R1  r13 shf

    x0 = imad(x1, one, x0);  x1 = MROT_XOR(x1, m15, x0);        // R2  r15 mul
    x0 = imad(x1, one, x0);  x1 = MROT_XOR(x1, m26, x0);        // R3  r26 mul
    x0 = imad(x1, one, x0);  x1 = rotl32(x1, 6)  ^ x0;          // R4  r6  shf

    x0 = imad(ks1, one, x0);           // inject 1
    x1 = imad(ks2 + 1u, one, x1);

    x0 = imad(x1, one, x0);  x1 = rotl32(x1, 17) ^ x0;          // R5  r17 shf
    x0 = imad(x1, one, x0);  x1 = MROT_XOR(x1, m29, x0);        // R6  r29 mul
    x0 = imad(x1, one, x0);  x1 = rotl32(x1, 16) ^ x0;          // R7  r16 shf
    x0 = imad(x1, one, x0);  x1 = rotl32(x1, 24) ^ x0;          // R8  r24 shf

    x0 = imad(ks2, one, x0);           // inject 2
    x1 = imad(2u, one, x1);

    x0 = imad(x1, one, x0);  x1 = rotl32(x1, 13) ^ x0;          // R9  r13 shf
    x0 = imad(x1, one, x0);  x1 = MROT_XOR(x1, m15, x0);        // R10 r15 mul
    x0 = imad(x1, one, x0);  x1 = MROT_XOR(x1, m26, x0);        // R11 r26 mul
    x0 = imad(x1, one, x0);  x1 = rotl32(x1, 6)  ^ x0;          // R12 r6  shf

    x0 = x0;                           // inject 3: +ks0 = 0
    x1 = imad(ks1 + 3u, one, x1);

    x0 = imad(x1, one, x0);  x1 = rotl32(x1, 17) ^ x0;          // R13 r17 shf
    x0 = imad(x1, one, x0);  x1 = rotl32(x1, 29) ^ x0;          // R14 r29 shf
    x0 = imad(x1, one, x0);  x1 = rotl32(x1, 16) ^ x0;          // R15 r16 shf
    x0 = imad(x1, one, x0);  x1 = rotl32(x1, 24) ^ x0;          // R16 r24 shf

    x0 = imad(ks1, one, x0);           // inject 4
    x1 = imad(ks2 + 4u, one, x1);

    x0 = imad(x1, one, x0);  x1 = rotl32(x1, 13) ^ x0;          // R17 r13 shf
    x0 = imad(x1, one, x0);  x1 = rotl32(x1, 15) ^ x0;          // R18 r15 shf
    x0 = imad(x1, one, x0);  x1 = MROT_XOR(x1, m26, x0);        // R19 r26 mul
    x0 = imad(x1, one, x0);  x1 = rotl32(x1, 6)  ^ x0;          // R20 r6  shf

    x0 = imad(ks2, one, x0);           // inject 5
    x1 = imad(5u, one, x1);

    return x0 ^ x1;
}

// ---------------------------------------------------------------------------
// Kernel 1: precompute s[o,k] = d + a * sigmoid(dx * (w - x0)), float4.
// ---------------------------------------------------------------------------
__global__ void sls_sigmoid_kernel(const float4* __restrict__ w,
                                   const float4* __restrict__ x0,
                                   const float4* __restrict__ dx,
                                   const float4* __restrict__ a,
                                   const float4* __restrict__ d) {
    int i = blockIdx.x * blockDim.x + threadIdx.x;
    if (i < (OUT_DIM * IN_DIM) / 4) {
        float4 wv = w[i], xv = x0[i], dxv = dx[i], av = a[i], dv = d[i];
        float4 r;
        r.x = dv.x + av.x / (1.0f + expf(-dxv.x * (wv.x - xv.x)));
        r.y = dv.y + av.y / (1.0f + expf(-dxv.y * (wv.y - xv.y)));
        r.z = dv.z + av.z / (1.0f + expf(-dxv.z * (wv.z - xv.z)));
        r.w = dv.w + av.w / (1.0f + expf(-dxv.w * (wv.w - xv.w)));
        ((float4*)g_sig)[i] = r;
    }
}

// ---------------------------------------------------------------------------
// Kernel 2: one warp per (b, o); lane processes 8 float4 chunks (32 k).
// Loads are software-pipelined one chunk ahead (branchless wrap index).
// Compare: bitcast((bits>>9) + 0x3f800000) < fma(in, s, 1.0f)
//   (exact: u = v-1, clamp is a no-op since in,s in [0,1)).
// ---------------------------------------------------------------------------
__global__ void __launch_bounds__(256)
sls_main_kernel(const float* __restrict__ input,
                const float* __restrict__ bias,
                float* __restrict__ out,
                uint32_t one) {
    int gtid = blockIdx.x * blockDim.x + threadIdx.x;
    int w    = gtid >> 5;            // warp id: 0 .. 128*1024-1
    int lane = gtid & 31;

    int o = w & (OUT_DIM - 1);       // 0..1023
    int b = w >> 10;                 // 0..127

    const float4* __restrict__ s4 = (const float4*)(g_sig + o * IN_DIM);
    const float4* __restrict__ i4 = (const float4*)(input + b * IN_DIM);

    const uint32_t m15 = one << 15;
    const uint32_t m26 = one << 26;
    const uint32_t m29 = one << 29;
    const uint32_t expo = imul_lo(one, 0x3f800000u);  // opaque, kept in reg

    // flattened element index for (b, o, lane*4): i = b*2^20 + o*2^10 + k
    uint32_t tbase = ((uint32_t)b << 20) + ((uint32_t)o << 10) + ((uint32_t)lane << 2);

    int cnt = 0;

    // prefetch chunk 0
    float4 iv = i4[lane];
    float4 sv = s4[lane];

#pragma unroll 2
    for (int j = 0; j < 8; j++) {
        // prefetch next chunk (wraps to chunk 0 on last iter; in-bounds, unused)
        int nidx = (((j + 1) & 7) << 5) + lane;
        float4 niv = i4[nidx];
        float4 nsv = s4[nidx];

        uint32_t c = tbase + ((uint32_t)j << 7);

        {
            uint32_t bits = threefry_bits_42(c + 0u, one, m15, m26, m29);
            float v = __uint_as_float(imad(bits >> 9, one, expo));
            cnt += (v < __fmaf_rn(iv.x, sv.x, 1.0f)) ? 1 : 0;
        }
        {
            uint32_t bits = threefry_bits_42(c + 1u, one, m15, m26, m29);
            float v = __uint_as_float(imad(bits >> 9, one, expo));
            cnt += (v < __fmaf_rn(iv.y, sv.y, 1.0f)) ? 1 : 0;
        }
        {
            uint32_t bits = threefry_bits_42(c + 2u, one, m15, m26, m29);
            float v = __uint_as_float(imad(bits >> 9, one, expo));
            cnt += (v < __fmaf_rn(iv.z, sv.z, 1.0f)) ? 1 : 0;
        }
        {
            uint32_t bits = threefry_bits_42(c + 3u, one, m15, m26, m29);
            float v = __uint_as_float(imad(bits >> 9, one, expo));
            cnt += (v < __fmaf_rn(iv.w, sv.w, 1.0f)) ? 1 : 0;
        }

        iv = niv;
        sv = nsv;
    }

    cnt = __reduce_add_sync(0xffffffffu, cnt);

    if (lane == 0) {
        out[b * OUT_DIM + o] = (float)cnt + bias[o];
    }
}

// ---------------------------------------------------------------------------
// kernel_launch
// Inputs (metadata order): input(128*1024), weight(1024*1024), bias(1024),
//                          x0, dx, a, d (each 1024*1024)
// Output: (128, 1024) float32
// ---------------------------------------------------------------------------
extern "C" void kernel_launch(void* const* d_in, const int* in_sizes, int n_in,
                              void* d_out, int out_size) {
    const float* input  = (const float*)d_in[0];
    const float* weight = (const float*)d_in[1];
    const float* bias   = (const float*)d_in[2];
    const float* x0     = (const float*)d_in[3];
    const float* dx     = (const float*)d_in[4];
    const float* a      = (const float*)d_in[5];
    const float* d      = (const float*)d_in[6];
    float* out          = (float*)d_out;

    // Kernel 1: sigmoid table (1M elements, float4)
    {
        int threads = 256;
        int n4      = (OUT_DIM * IN_DIM) / 4;
        int blocks  = (n4 + threads - 1) / threads;
        sls_sigmoid_kernel<<<blocks, threads>>>((const float4*)weight,
                                                (const float4*)x0,
                                                (const float4*)dx,
                                                (const float4*)a,
                                                (const float4*)d);
    }

    // Kernel 2: 128*1024 warps, 8 warps/block -> 16384 blocks
    {
        int threads = 256;
        int blocks  = (B_DIM * OUT_DIM * 32) / threads;  // 16384
        sls_main_kernel<<<blocks, threads>>>(input, bias, out, 1u);
    }
}

// round 6
// speedup vs baseline: 1.0300x; 1.0300x over previous
#include <cuda_runtime.h>
#include <cstdint>

// Problem constants
#define B_DIM   128
#define OUT_DIM 1024
#define IN_DIM  1024

// Scratch: s[o,k] = d + a * sigmoid(dx * (w - x0))  (4 MB, static device array)
__device__ float g_sig[OUT_DIM * IN_DIM];

// ---------------------------------------------------------------------------
// Pipe-steering helpers. `one` is a runtime kernel argument equal to 1 so
// ptxas cannot fold it; mad.lo.u32 with multiplier `one` is an IMAD on the
// fma pipe instead of an IADD3 on the alu pipe.
// ---------------------------------------------------------------------------
__device__ __forceinline__ uint32_t imad(uint32_t a, uint32_t b, uint32_t c) {
    uint32_t r;
    asm("mad.lo.u32 %0, %1, %2, %3;" : "=r"(r) : "r"(a), "r"(b), "r"(c));
    return r;
}
__device__ __forceinline__ uint32_t imul_lo(uint32_t a, uint32_t b) {
    uint32_t r;
    asm("mul.lo.u32 %0, %1, %2;" : "=r"(r) : "r"(a), "r"(b));
    return r;
}
__device__ __forceinline__ uint32_t rotl32(uint32_t x, int r) {
    return __funnelshift_l(x, x, r);
}
// Wide-mul rotate fused with xor:
//   x * 2^r -> 64-bit (lo,hi) in ONE IMAD.WIDE.U32 (fma pipe);
//   (lo | hi) ^ x0 is ONE LOP3 (alu pipe).
// Same issue count as SHF+LOP3 but only 1 alu op instead of 2.
__device__ __forceinline__ uint32_t wrot_xor(uint32_t x1, uint32_t m, uint32_t x0) {
    uint64_t r;
    asm("mul.wide.u32 %0, %1, %2;" : "=l"(r) : "r"(x1), "r"(m));
    uint32_t lo = (uint32_t)r;
    uint32_t hi = (uint32_t)(r >> 32);
    return (lo | hi) ^ x0;
}

// ---------------------------------------------------------------------------
// threefry2x32, key = (0, 42); partitionable random_bits:
//   ctr = (0, i), bits = out0 ^ out1.
//   ks1 = 42, ks2 = 42 ^ 0x1BD11BDA = 0x1BD11BF0
// All adds/injections as IMAD (fma pipe). 5 of 20 rotates as IMAD.WIDE
// rotates (fma pipe) to balance alu vs fma at equal issue count.
// ---------------------------------------------------------------------------
__device__ __forceinline__ uint32_t threefry_bits_42(uint32_t i, uint32_t one,
                                                     uint32_t m26, uint32_t m29) {
    const uint32_t ks1 = 42u, ks2 = 0x1BD11BF0u;

    uint32_t x1 = imad(i, one, ks1);   // setup (fma)
    uint32_t x0 = x1;                  // round-1 add with x0_init = 0 folded
    x1 = rotl32(x1, 13) ^ x0;                                   // R1  r13 shf

    x0 = imad(x1, one, x0);  x1 = rotl32(x1, 15) ^ x0;          // R2  r15 shf
    x0 = imad(x1, one, x0);  x1 = wrot_xor(x1, m26, x0);        // R3  r26 WIDE
    x0 = imad(x1, one, x0);  x1 = rotl32(x1, 6)  ^ x0;          // R4  r6  shf

    x0 = imad(ks1, one, x0);           // inject 1
    x1 = imad(ks2 + 1u, one, x1);

    x0 = imad(x1, one, x0);  x1 = rotl32(x1, 17) ^ x0;          // R5  r17 shf
    x0 = imad(x1, one, x0);  x1 = wrot_xor(x1, m29, x0);        // R6  r29 WIDE
    x0 = imad(x1, one, x0);  x1 = rotl32(x1, 16) ^ x0;          // R7  r16 shf
    x0 = imad(x1, one, x0);  x1 = rotl32(x1, 24) ^ x0;          // R8  r24 shf

    x0 = imad(ks2, one, x0);           // inject 2
    x1 = imad(2u, one, x1);

    x0 = imad(x1, one, x0);  x1 = rotl32(x1, 13) ^ x0;          // R9  r13 shf
    x0 = imad(x1, one, x0);  x1 = rotl32(x1, 15) ^ x0;          // R10 r15 shf
    x0 = imad(x1, one, x0);  x1 = wrot_xor(x1, m26, x0);        // R11 r26 WIDE
    x0 = imad(x1, one, x0);  x1 = rotl32(x1, 6)  ^ x0;          // R12 r6  shf

    /* inject 3: x0 += ks0 = 0 (no-op) */
    x1 = imad(ks1 + 3u, one, x1);

    x0 = imad(x1, one, x0);  x1 = rotl32(x1, 17) ^ x0;          // R13 r17 shf
    x0 = imad(x1, one, x0);  x1 = wrot_xor(x1, m29, x0);        // R14 r29 WIDE
    x0 = imad(x1, one, x0);  x1 = rotl32(x1, 16) ^ x0;          // R15 r16 shf
    x0 = imad(x1, one, x0);  x1 = rotl32(x1, 24) ^ x0;          // R16 r24 shf

    x0 = imad(ks1, one, x0);           // inject 4
    x1 = imad(ks2 + 4u, one, x1);

    x0 = imad(x1, one, x0);  x1 = rotl32(x1, 13) ^ x0;          // R17 r13 shf
    x0 = imad(x1, one, x0);  x1 = rotl32(x1, 15) ^ x0;          // R18 r15 shf
    x0 = imad(x1, one, x0);  x1 = wrot_xor(x1, m26, x0);        // R19 r26 WIDE
    x0 = imad(x1, one, x0);  x1 = rotl32(x1, 6)  ^ x0;          // R20 r6  shf

    x0 = imad(ks2, one, x0);           // inject 5
    x1 = imad(5u, one, x1);

    return x0 ^ x1;
}

// ---------------------------------------------------------------------------
// Kernel 1: precompute s[o,k] = d + a * sigmoid(dx * (w - x0)), float4.
// ---------------------------------------------------------------------------
__global__ void sls_sigmoid_kernel(const float4* __restrict__ w,
                                   const float4* __restrict__ x0,
                                   const float4* __restrict__ dx,
                                   const float4* __restrict__ a,
                                   const float4* __restrict__ d) {
    int i = blockIdx.x * blockDim.x + threadIdx.x;
    if (i < (OUT_DIM * IN_DIM) / 4) {
        float4 wv = w[i], xv = x0[i], dxv = dx[i], av = a[i], dv = d[i];
        float4 r;
        r.x = dv.x + av.x / (1.0f + expf(-dxv.x * (wv.x - xv.x)));
        r.y = dv.y + av.y / (1.0f + expf(-dxv.y * (wv.y - xv.y)));
        r.z = dv.z + av.z / (1.0f + expf(-dxv.z * (wv.z - xv.z)));
        r.w = dv.w + av.w / (1.0f + expf(-dxv.w * (wv.w - xv.w)));
        ((float4*)g_sig)[i] = r;
    }
}

// ---------------------------------------------------------------------------
// Kernel 2: one warp per (b, o); lane processes 8 float4 chunks (32 k).
// Compare: bitcast((bits>>9) + 0x3f800000) < fma(in, s, 1.0f)
//   (exact: u = v-1; clamp is a data no-op since in,s in [0,1)).
// ---------------------------------------------------------------------------
__global__ void __launch_bounds__(256)
sls_main_kernel(const float* __restrict__ input,
                const float* __restrict__ bias,
                float* __restrict__ out,
                uint32_t one) {
    int gtid = blockIdx.x * blockDim.x + threadIdx.x;
    int w    = gtid >> 5;            // warp id: 0 .. 128*1024-1
    int lane = gtid & 31;

    int o = w & (OUT_DIM - 1);       // 0..1023
    int b = w >> 10;                 // 0..127

    const float4* __restrict__ s4 = (const float4*)(g_sig + o * IN_DIM);
    const float4* __restrict__ i4 = (const float4*)(input + b * IN_DIM);

    const uint32_t m26 = one << 26;
    const uint32_t m29 = one << 29;
    const uint32_t expo = imul_lo(one, 0x3f800000u);  // opaque, kept in reg

    // flattened element index for (b, o, lane*4): i = b*2^20 + o*2^10 + k
    uint32_t tbase = ((uint32_t)b << 20) + ((uint32_t)o << 10) + ((uint32_t)lane << 2);

    int cnt = 0;

#pragma unroll 1
    for (int j = 0; j < 8; j++) {
        int idx = (j << 5) + lane;       // float4 index, coalesced
        float4 iv = i4[idx];
        float4 sv = s4[idx];
        uint32_t c = tbase + ((uint32_t)j << 7);

        {
            uint32_t bits = threefry_bits_42(c + 0u, one, m26, m29);
            float v = __uint_as_float(imad(bits >> 9, one, expo));
            cnt += (v < __fmaf_rn(iv.x, sv.x, 1.0f)) ? 1 : 0;
        }
        {
            uint32_t bits = threefry_bits_42(c + 1u, one, m26, m29);
            float v = __uint_as_float(imad(bits >> 9, one, expo));
            cnt += (v < __fmaf_rn(iv.y, sv.y, 1.0f)) ? 1 : 0;
        }
        {
            uint32_t bits = threefry_bits_42(c + 2u, one, m26, m29);
            float v = __uint_as_float(imad(bits >> 9, one, expo));
            cnt += (v < __fmaf_rn(iv.z, sv.z, 1.0f)) ? 1 : 0;
        }
        {
            uint32_t bits = threefry_bits_42(c + 3u, one, m26, m29);
            float v = __uint_as_float(imad(bits >> 9, one, expo));
            cnt += (v < __fmaf_rn(iv.w, sv.w, 1.0f)) ? 1 : 0;
        }
    }

    cnt = __reduce_add_sync(0xffffffffu, cnt);

    if (lane == 0) {
        out[b * OUT_DIM + o] = (float)cnt + bias[o];
    }
}

// ---------------------------------------------------------------------------
// kernel_launch
// Inputs (metadata order): input(128*1024), weight(1024*1024), bias(1024),
//                          x0, dx, a, d (each 1024*1024)
// Output: (128, 1024) float32
// ---------------------------------------------------------------------------
extern "C" void kernel_launch(void* const* d_in, const int* in_sizes, int n_in,
                              void* d_out, int out_size) {
    const float* input  = (const float*)d_in[0];
    const float* weight = (const float*)d_in[1];
    const float* bias   = (const float*)d_in[2];
    const float* x0     = (const float*)d_in[3];
    const float* dx     = (const float*)d_in[4];
    const float* a      = (const float*)d_in[5];
    const float* d      = (const float*)d_in[6];
    float* out          = (float*)d_out;

    // Kernel 1: sigmoid table (1M elements, float4)
    {
        int threads = 256;
        int n4      = (OUT_DIM * IN_DIM) / 4;
        int blocks  = (n4 + threads - 1) / threads;
        sls_sigmoid_kernel<<<blocks, threads>>>((const float4*)weight,
                                                (const float4*)x0,
                                                (const float4*)dx,
                                                (const float4*)a,
                                                (const float4*)d);
    }

    // Kernel 2: 128*1024 warps, 8 warps/block -> 16384 blocks
    {
        int threads = 256;
        int blocks  = (B_DIM * OUT_DIM * 32) / threads;  // 16384
        sls_main_kernel<<<blocks, threads>>>(input, bias, out, 1u);
    }
}

// round 7
// speedup vs baseline: 1.0733x; 1.0421x over previous
#include <cuda_runtime.h>
#include <cstdint>

// Problem constants
#define B_DIM   128
#define OUT_DIM 1024
#define IN_DIM  1024

// Scratch: s[o,k] = d + a * sigmoid(dx * (w - x0))  (4 MB, static device array)
__device__ float g_sig[OUT_DIM * IN_DIM];

// ---------------------------------------------------------------------------
// Pipe-steering helpers. `one` is a runtime kernel argument equal to 1 so
// ptxas cannot fold it; mad.lo.u32 with multiplier `one` is an IMAD on the
// fma pipe instead of an IADD3 on the alu pipe.
// ---------------------------------------------------------------------------
__device__ __forceinline__ uint32_t imad(uint32_t a, uint32_t b, uint32_t c) {
    uint32_t r;
    asm("mad.lo.u32 %0, %1, %2, %3;" : "=r"(r) : "r"(a), "r"(b), "r"(c));
    return r;
}
__device__ __forceinline__ uint32_t imul_lo(uint32_t a, uint32_t b) {
    uint32_t r;
    asm("mul.lo.u32 %0, %1, %2;" : "=r"(r) : "r"(a), "r"(b));
    return r;
}
__device__ __forceinline__ uint32_t rotl32(uint32_t x, int r) {
    return __funnelshift_l(x, x, r);
}
// Wide-mul rotate fused with xor:
//   x * 2^r -> 64-bit (lo,hi) in ONE IMAD.WIDE.U32 (fma pipe);
//   (lo | hi) ^ x0 is ONE LOP3 (alu pipe).
__device__ __forceinline__ uint32_t wrot_xor(uint32_t x1, uint32_t m, uint32_t x0) {
    uint64_t r;
    asm("mul.wide.u32 %0, %1, %2;" : "=l"(r) : "r"(x1), "r"(m));
    uint32_t lo = (uint32_t)r;
    uint32_t hi = (uint32_t)(r >> 32);
    return (lo | hi) ^ x0;
}

// ---------------------------------------------------------------------------
// threefry2x32, key = (0, 42); partitionable random_bits:
//   ctr = (0, i), bits = out0 ^ out1.
//   ks1 = 42, ks2 = 42 ^ 0x1BD11BDA = 0x1BD11BF0
// Identical to R6 (measured alu share 0.486): adds/injections on IMAD,
// 5 of 20 rotates as IMAD.WIDE.
// ---------------------------------------------------------------------------
__device__ __forceinline__ uint32_t threefry_bits_42(uint32_t i, uint32_t one,
                                                     uint32_t m26, uint32_t m29) {
    const uint32_t ks1 = 42u, ks2 = 0x1BD11BF0u;

    uint32_t x1 = imad(i, one, ks1);   // setup (fma)
    uint32_t x0 = x1;                  // round-1 add with x0_init = 0 folded
    x1 = rotl32(x1, 13) ^ x0;                                   // R1  r13 shf

    x0 = imad(x1, one, x0);  x1 = rotl32(x1, 15) ^ x0;          // R2  r15 shf
    x0 = imad(x1, one, x0);  x1 = wrot_xor(x1, m26, x0);        // R3  r26 WIDE
    x0 = imad(x1, one, x0);  x1 = rotl32(x1, 6)  ^ x0;          // R4  r6  shf

    x0 = imad(ks1, one, x0);           // inject 1
    x1 = imad(ks2 + 1u, one, x1);

    x0 = imad(x1, one, x0);  x1 = rotl32(x1, 17) ^ x0;          // R5  r17 shf
    x0 = imad(x1, one, x0);  x1 = wrot_xor(x1, m29, x0);        // R6  r29 WIDE
    x0 = imad(x1, one, x0);  x1 = rotl32(x1, 16) ^ x0;          // R7  r16 shf
    x0 = imad(x1, one, x0);  x1 = rotl32(x1, 24) ^ x0;          // R8  r24 shf

    x0 = imad(ks2, one, x0);           // inject 2
    x1 = imad(2u, one, x1);

    x0 = imad(x1, one, x0);  x1 = rotl32(x1, 13) ^ x0;          // R9  r13 shf
    x0 = imad(x1, one, x0);  x1 = rotl32(x1, 15) ^ x0;          // R10 r15 shf
    x0 = imad(x1, one, x0);  x1 = wrot_xor(x1, m26, x0);        // R11 r26 WIDE
    x0 = imad(x1, one, x0);  x1 = rotl32(x1, 6)  ^ x0;          // R12 r6  shf

    /* inject 3: x0 += ks0 = 0 (no-op) */
    x1 = imad(ks1 + 3u, one, x1);

    x0 = imad(x1, one, x0);  x1 = rotl32(x1, 17) ^ x0;          // R13 r17 shf
    x0 = imad(x1, one, x0);  x1 = wrot_xor(x1, m29, x0);        // R14 r29 WIDE
    x0 = imad(x1, one, x0);  x1 = rotl32(x1, 16) ^ x0;          // R15 r16 shf
    x0 = imad(x1, one, x0);  x1 = rotl32(x1, 24) ^ x0;          // R16 r24 shf

    x0 = imad(ks1, one, x0);           // inject 4
    x1 = imad(ks2 + 4u, one, x1);

    x0 = imad(x1, one, x0);  x1 = rotl32(x1, 13) ^ x0;          // R17 r13 shf
    x0 = imad(x1, one, x0);  x1 = rotl32(x1, 15) ^ x0;          // R18 r15 shf
    x0 = imad(x1, one, x0);  x1 = wrot_xor(x1, m26, x0);        // R19 r26 WIDE
    x0 = imad(x1, one, x0);  x1 = rotl32(x1, 6)  ^ x0;          // R20 r6  shf

    x0 = imad(ks2, one, x0);           // inject 5
    x1 = imad(5u, one, x1);

    return x0 ^ x1;
}

// ---------------------------------------------------------------------------
// Kernel 1: precompute s[o,k] = d + a * sigmoid(dx * (w - x0)), float4.
// ---------------------------------------------------------------------------
__global__ void sls_sigmoid_kernel(const float4* __restrict__ w,
                                   const float4* __restrict__ x0,
                                   const float4* __restrict__ dx,
                                   const float4* __restrict__ a,
                                   const float4* __restrict__ d) {
    int i = blockIdx.x * blockDim.x + threadIdx.x;
    if (i < (OUT_DIM * IN_DIM) / 4) {
        float4 wv = w[i], xv = x0[i], dxv = dx[i], av = a[i], dv = d[i];
        float4 r;
        r.x = dv.x + av.x / (1.0f + expf(-dxv.x * (wv.x - xv.x)));
        r.y = dv.y + av.y / (1.0f + expf(-dxv.y * (wv.y - xv.y)));
        r.z = dv.z + av.z / (1.0f + expf(-dxv.z * (wv.z - xv.z)));
        r.w = dv.w + av.w / (1.0f + expf(-dxv.w * (wv.w - xv.w)));
        ((float4*)g_sig)[i] = r;
    }
}

// ---------------------------------------------------------------------------
// Kernel 2: block = one output column o shared by 8 warps (one per b in the
// block's b-group). The sig row for o is staged in shared memory once per
// block; inner loop reads it via conflict-free LDS.128 (lat 29, no L2
// exposure). Input row stays LDG (hot in L2/L1). One LDG per chunk instead
// of two.
// Compare: bitcast((bits>>9) + 0x3f800000) < fma(in, s, 1.0f).
// ---------------------------------------------------------------------------
__global__ void __launch_bounds__(256)
sls_main_kernel(const float* __restrict__ input,
                const float* __restrict__ bias,
                float* __restrict__ out,
                uint32_t one) {
    __shared__ float s_sig[IN_DIM];            // 4 KB

    int o      = blockIdx.x & (OUT_DIM - 1);   // 0..1023
    int bgroup = blockIdx.x >> 10;             // 0..15
    int tid    = threadIdx.x;
    int warp   = tid >> 5;                     // 0..7
    int lane   = tid & 31;
    int b      = (bgroup << 3) + warp;         // 0..127

    // stage sig row o: 1024 floats, 256 threads, one float4 each
    {
        const float4* __restrict__ g4 = (const float4*)(g_sig + o * IN_DIM);
        ((float4*)s_sig)[tid] = g4[tid];
    }
    __syncthreads();

    const float4* __restrict__ i4 = (const float4*)(input + b * IN_DIM);
    const float4* __restrict__ s4 = (const float4*)s_sig;

    const uint32_t m26 = one << 26;
    const uint32_t m29 = one << 29;
    const uint32_t expo = imul_lo(one, 0x3f800000u);  // opaque, kept in reg

    // flattened element index for (b, o, lane*4): i = b*2^20 + o*2^10 + k
    uint32_t tbase = ((uint32_t)b << 20) + ((uint32_t)o << 10) + ((uint32_t)lane << 2);

    int cnt = 0;

#pragma unroll 1
    for (int j = 0; j < 8; j++) {
        int idx = (j << 5) + lane;       // float4 index, coalesced
        float4 iv = i4[idx];             // LDG (L2-hot)
        float4 sv = s4[idx];             // LDS.128, conflict-free
        uint32_t c = tbase + ((uint32_t)j << 7);

        {
            uint32_t bits = threefry_bits_42(c + 0u, one, m26, m29);
            float v = __uint_as_float(imad(bits >> 9, one, expo));
            cnt += (v < __fmaf_rn(iv.x, sv.x, 1.0f)) ? 1 : 0;
        }
        {
            uint32_t bits = threefry_bits_42(c + 1u, one, m26, m29);
            float v = __uint_as_float(imad(bits >> 9, one, expo));
            cnt += (v < __fmaf_rn(iv.y, sv.y, 1.0f)) ? 1 : 0;
        }
        {
            uint32_t bits = threefry_bits_42(c + 2u, one, m26, m29);
            float v = __uint_as_float(imad(bits >> 9, one, expo));
            cnt += (v < __fmaf_rn(iv.z, sv.z, 1.0f)) ? 1 : 0;
        }
        {
            uint32_t bits = threefry_bits_42(c + 3u, one, m26, m29);
            float v = __uint_as_float(imad(bits >> 9, one, expo));
            cnt += (v < __fmaf_rn(iv.w, sv.w, 1.0f)) ? 1 : 0;
        }
    }

    cnt = __reduce_add_sync(0xffffffffu, cnt);

    if (lane == 0) {
        out[b * OUT_DIM + o] = (float)cnt + bias[o];
    }
}

// ---------------------------------------------------------------------------
// kernel_launch
// Inputs (metadata order): input(128*1024), weight(1024*1024), bias(1024),
//                          x0, dx, a, d (each 1024*1024)
// Output: (128, 1024) float32
// ---------------------------------------------------------------------------
extern "C" void kernel_launch(void* const* d_in, const int* in_sizes, int n_in,
                              void* d_out, int out_size) {
    const float* input  = (const float*)d_in[0];
    const float* weight = (const float*)d_in[1];
    const float* bias   = (const float*)d_in[2];
    const float* x0     = (const float*)d_in[3];
    const float* dx     = (const float*)d_in[4];
    const float* a      = (const float*)d_in[5];
    const float* d      = (const float*)d_in[6];
    float* out          = (float*)d_out;

    // Kernel 1: sigmoid table (1M elements, float4)
    {
        int threads = 256;
        int n4      = (OUT_DIM * IN_DIM) / 4;
        int blocks  = (n4 + threads - 1) / threads;
        sls_sigmoid_kernel<<<blocks, threads>>>((const float4*)weight,
                                                (const float4*)x0,
                                                (const float4*)dx,
                                                (const float4*)a,
                                                (const float4*)d);
    }

    // Kernel 2: 16384 blocks of 256 threads (8 warps share one sig row)
    {
        int threads = 256;
        int blocks  = B_DIM / 8 * OUT_DIM;   // 16 bgroups * 1024 o = 16384
        sls_main_kernel<<<blocks, threads>>>(input, bias, out, 1u);
    }
}